// round 6
// baseline (speedup 1.0000x reference)
#include <cuda_runtime.h>
#include <cuda_fp16.h>
#include <cstdint>

#define N_NODES 100000
#define D_FEAT  128
#define HIDDEN  128
#define M_TILE  128
#define KPAD    136          // fp16 row stride (272 B) -> conflict-free fragment loads

// ---------------------------------------------------------------------------
// Global scratch.  A/B stored fp16 (51 MB working set -> L2-resident gathers).
// ---------------------------------------------------------------------------
__device__ __half g_A[N_NODES * HIDDEN];       // x @ W1[:128] + b1
__device__ __half g_B[N_NODES * HIDDEN];       // x @ W1[128:]
__device__ __half g_Wh[256 * KPAD];            // Wfull^T padded, fp16

// ---------------------------------------------------------------------------
// Prep: Wfull[k][n] (256 cols n) -> g_Wh[n][k] fp16.
// ---------------------------------------------------------------------------
__global__ __launch_bounds__(256) void prep_w_kernel(const float* __restrict__ W1)
{
    int i = blockIdx.x * 256 + threadIdx.x;    // n*128 + k
    if (i >= 256 * 128) return;
    int n = i >> 7, k = i & 127;
    int r = (n < 128) ? k : (128 + k);
    int c = (n < 128) ? n : (n - 128);
    g_Wh[n * KPAD + k] = __float2half_rn(W1[r * 128 + c]);
}

// ---------------------------------------------------------------------------
// Stage 1: C[128 nodes][256 cols] per CTA via mma.sync m16n8k16 fp16 (fp32 acc).
// 512 threads, 16 warps in 4x4 grid of 32(M) x 64(N) warp tiles, single pass.
// SMEM: sX [128][KPAD] + sW [256][KPAD] fp16 = 104448 B -> 2 CTAs/SM.
// ---------------------------------------------------------------------------
#define SM_X 0
#define SM_W 34816
#define SMEM_TOTAL 104448

static __device__ __forceinline__ uint32_t smem_u32(const void* p) {
    uint32_t a;
    asm("{ .reg .u64 t; cvta.to.shared.u64 t, %1; cvt.u32.u64 %0, t; }" : "=r"(a) : "l"(p));
    return a;
}

static __device__ __forceinline__ void mma_fp16(
    float c[4], const uint32_t a[4], const uint32_t b[2])
{
    asm volatile(
        "mma.sync.aligned.m16n8k16.row.col.f32.f16.f16.f32 "
        "{%0,%1,%2,%3}, {%4,%5,%6,%7}, {%8,%9}, {%0,%1,%2,%3};"
        : "+f"(c[0]), "+f"(c[1]), "+f"(c[2]), "+f"(c[3])
        : "r"(a[0]), "r"(a[1]), "r"(a[2]), "r"(a[3]), "r"(b[0]), "r"(b[1]));
}

__global__ __launch_bounds__(512) void node_gemm_kernel(
    const float* __restrict__ x,
    const float* __restrict__ b1)
{
    extern __shared__ char smem[];
    __half* sX = (__half*)(smem + SM_X);
    __half* sW = (__half*)(smem + SM_W);

    const int tid     = threadIdx.x;
    const int m_block = blockIdx.x * M_TILE;

    // ---- W copy via cp.async (overlaps with X load+convert)
    {
        const uint32_t sw = smem_u32(sW);
        const char* gw = (const char*)g_Wh;
        #pragma unroll 2
        for (int i = tid * 16; i < 256 * KPAD * 2; i += 512 * 16)
            asm volatile("cp.async.cg.shared.global [%0], [%1], 16;"
                         :: "r"(sw + i), "l"(gw + i));
        asm volatile("cp.async.commit_group;");
    }

    // ---- load X tile (128 x 128 fp32) -> fp16
    for (int i = tid; i < M_TILE * 64; i += 512) {
        int m = i >> 6;
        int k = (i & 63) * 2;
        int gm = m_block + m;
        float2 v = make_float2(0.f, 0.f);
        if (gm < N_NODES) v = *(const float2*)&x[gm * D_FEAT + k];
        *(__half2*)&sX[m * KPAD + k] = __floats2half2_rn(v.x, v.y);
    }
    asm volatile("cp.async.wait_group 0;");
    __syncthreads();

    // ---- warp tiling: 16 warps, each 32(M) x 64(N)
    const int wid  = tid >> 5;
    const int lane = tid & 31;
    const int g    = lane >> 2;
    const int t    = lane & 3;
    const int mrow0 = (wid & 3) * 32;
    const int ncol0 = (wid >> 2) * 64;     // 0,64,128,192

    float acc[2][8][4];
    #pragma unroll
    for (int mt = 0; mt < 2; mt++)
        #pragma unroll
        for (int nt = 0; nt < 8; nt++)
            #pragma unroll
            for (int r = 0; r < 4; r++) acc[mt][nt][r] = 0.f;

    #pragma unroll
    for (int ks = 0; ks < 8; ks++) {
        const int k0 = ks * 16;
        uint32_t a[2][4];
        #pragma unroll
        for (int mt = 0; mt < 2; mt++) {
            const int rb = mrow0 + mt * 16;
            a[mt][0] = *(const uint32_t*)&sX[(rb + g)     * KPAD + k0 + t * 2];
            a[mt][1] = *(const uint32_t*)&sX[(rb + g + 8) * KPAD + k0 + t * 2];
            a[mt][2] = *(const uint32_t*)&sX[(rb + g)     * KPAD + k0 + t * 2 + 8];
            a[mt][3] = *(const uint32_t*)&sX[(rb + g + 8) * KPAD + k0 + t * 2 + 8];
        }
        #pragma unroll
        for (int nt = 0; nt < 8; nt++) {
            const int cb = ncol0 + nt * 8;
            uint32_t b[2];
            b[0] = *(const uint32_t*)&sW[(cb + g) * KPAD + k0 + t * 2];
            b[1] = *(const uint32_t*)&sW[(cb + g) * KPAD + k0 + t * 2 + 8];
            mma_fp16(acc[0][nt], a[0], b);
            mma_fp16(acc[1][nt], a[1], b);
        }
    }

    // ---- epilogue: +b1 (A-half), fp16 store
    const bool isA = (ncol0 < 128);
    __half* halfp = isA ? g_A : g_B;
    const int clocal0 = isA ? ncol0 : (ncol0 - 128);

    float2 bb[8];
    #pragma unroll
    for (int nt = 0; nt < 8; nt++) {
        if (isA) bb[nt] = *(const float2*)&b1[ncol0 + nt * 8 + t * 2];
        else     bb[nt] = make_float2(0.f, 0.f);
    }
    #pragma unroll
    for (int mt = 0; mt < 2; mt++) {
        const int node0 = m_block + mrow0 + mt * 16 + g;
        const int node1 = node0 + 8;
        #pragma unroll
        for (int nt = 0; nt < 8; nt++) {
            const int c = clocal0 + nt * 8 + t * 2;
            if (node0 < N_NODES)
                *(__half2*)&halfp[(size_t)node0 * HIDDEN + c] =
                    __floats2half2_rn(acc[mt][nt][0] + bb[nt].x, acc[mt][nt][1] + bb[nt].y);
            if (node1 < N_NODES)
                *(__half2*)&halfp[(size_t)node1 * HIDDEN + c] =
                    __floats2half2_rn(acc[mt][nt][2] + bb[nt].x, acc[mt][nt][3] + bb[nt].y);
        }
    }
}

// ---------------------------------------------------------------------------
// Stage 2: full warp handles 4 edges per iteration.
// Each lane loads uint2 (4 halves) of each of the 8 gathered rows ->
// 8 independent LDG.64 in flight per lane.  Indices fetched coalesced by
// lanes 0-7 and shfl-broadcast.  fp16 add -> tanh.approx -> fp32 dot.
// ---------------------------------------------------------------------------
static __device__ __forceinline__ float tanh_fast(float x) {
    float y;
    asm("tanh.approx.f32 %0, %1;" : "=f"(y) : "f"(x));
    return y;
}

__global__ __launch_bounds__(256) void edge_kernel(
    const void*  __restrict__ idx,
    const float* __restrict__ W2,
    const float* __restrict__ b2,
    float*       __restrict__ out,
    int E)
{
    const int lane   = threadIdx.x & 31;
    const int gwarp  = (blockIdx.x * blockDim.x + threadIdx.x) >> 5;
    const int nwarps = (gridDim.x * blockDim.x) >> 5;

    const int* w32 = (const int*)idx;
    const bool is64 = ((w32[1] | w32[3] | w32[5] | w32[7]) == 0);
    const long long* p64 = (const long long*)idx;

    const float4 w4 = *(const float4*)&W2[lane * 4];
    const float bias2 = b2[0];

    const uint2* Au = (const uint2*)g_A;   // 32 uint2 per row
    const uint2* Bu = (const uint2*)g_B;

    const int Q = (E + 3) >> 2;            // groups of 4 edges
    for (int p = gwarp; p < Q; p += nwarps) {
        const int e0 = p * 4;

        // lanes 0-3 load src[e0..e0+3], lanes 4-7 load dst[e0..e0+3]
        int myidx = 0;
        if (lane < 8) {
            int e = e0 + (lane & 3);
            if (e >= E) e = E - 1;
            if (is64) myidx = (int)p64[(lane < 4 ? 0 : (size_t)E) + e];
            else      myidx = w32[(lane < 4 ? 0 : E) + e];
        }
        const int s0 = __shfl_sync(0xffffffffu, myidx, 0);
        const int s1 = __shfl_sync(0xffffffffu, myidx, 1);
        const int s2 = __shfl_sync(0xffffffffu, myidx, 2);
        const int s3 = __shfl_sync(0xffffffffu, myidx, 3);
        const int d0 = __shfl_sync(0xffffffffu, myidx, 4);
        const int d1 = __shfl_sync(0xffffffffu, myidx, 5);
        const int d2 = __shfl_sync(0xffffffffu, myidx, 6);
        const int d3 = __shfl_sync(0xffffffffu, myidx, 7);

        // 8 independent gathers in flight
        uint2 ua0 = __ldg(&Au[(size_t)s0 * 32 + lane]);
        uint2 ua1 = __ldg(&Au[(size_t)s1 * 32 + lane]);
        uint2 ua2 = __ldg(&Au[(size_t)s2 * 32 + lane]);
        uint2 ua3 = __ldg(&Au[(size_t)s3 * 32 + lane]);
        uint2 ub0 = __ldg(&Bu[(size_t)d0 * 32 + lane]);
        uint2 ub1 = __ldg(&Bu[(size_t)d1 * 32 + lane]);
        uint2 ub2 = __ldg(&Bu[(size_t)d2 * 32 + lane]);
        uint2 ub3 = __ldg(&Bu[(size_t)d3 * 32 + lane]);

        float acc0, acc1, acc2, acc3;
        {
            __half2 t0, t1;
            float2 f0, f1;
            #define EDGE_ACC(ua, ub, acc) do {                                  \
                t0 = __hadd2(*(const __half2*)&(ua).x, *(const __half2*)&(ub).x); \
                t1 = __hadd2(*(const __half2*)&(ua).y, *(const __half2*)&(ub).y); \
                f0 = __half22float2(t0);                                        \
                f1 = __half22float2(t1);                                        \
                acc = tanh_fast(f0.x) * w4.x;                                   \
                acc = fmaf(tanh_fast(f0.y), w4.y, acc);                         \
                acc = fmaf(tanh_fast(f1.x), w4.z, acc);                         \
                acc = fmaf(tanh_fast(f1.y), w4.w, acc);                         \
            } while (0)
            EDGE_ACC(ua0, ub0, acc0);
            EDGE_ACC(ua1, ub1, acc1);
            EDGE_ACC(ua2, ub2, acc2);
            EDGE_ACC(ua3, ub3, acc3);
            #undef EDGE_ACC
        }

        #pragma unroll
        for (int off = 16; off; off >>= 1) {
            acc0 += __shfl_xor_sync(0xffffffffu, acc0, off);
            acc1 += __shfl_xor_sync(0xffffffffu, acc1, off);
            acc2 += __shfl_xor_sync(0xffffffffu, acc2, off);
            acc3 += __shfl_xor_sync(0xffffffffu, acc3, off);
        }

        if (lane < 4) {
            float a = (lane == 0) ? acc0 : (lane == 1) ? acc1 : (lane == 2) ? acc2 : acc3;
            const int e = e0 + lane;
            if (e < E)
                out[e] = __fdividef(1.0f, 1.0f + __expf(-(a + bias2)));
        }
    }
}

// ---------------------------------------------------------------------------
extern "C" void kernel_launch(void* const* d_in, const int* in_sizes, int n_in,
                              void* d_out, int out_size)
{
    const float* x   = (const float*)d_in[0];
    const void*  idx = d_in[1];
    const float* W1  = (const float*)d_in[2];
    const float* b1  = (const float*)d_in[3];
    const float* W2  = (const float*)d_in[4];
    const float* b2  = (const float*)d_in[5];
    float* out = (float*)d_out;

    const int E = in_sizes[1] / 2;

    cudaFuncSetAttribute(node_gemm_kernel,
                         cudaFuncAttributeMaxDynamicSharedMemorySize, SMEM_TOTAL);

    prep_w_kernel<<<128, 256>>>(W1);

    const int n_tiles = (N_NODES + M_TILE - 1) / M_TILE;   // 782
    node_gemm_kernel<<<n_tiles, 512, SMEM_TOTAL>>>(x, b1);

    edge_kernel<<<1184, 256>>>(idx, W2, b2, out, E);
}